// round 11
// baseline (speedup 1.0000x reference)
#include <cuda_runtime.h>
#include <math.h>

#define KEEP 100
#define NCHUNK 18
#define MERGEW 1800
#define FULL 0xFFFFFFFFu

// ---------------- device scratch (no allocations) ----------------
__device__ float    gU[3][32][256];          // U_l[h][i] = sum_o sw1[h,o]*W_l[o,i]
__device__ float    gWt0[256 * 256];         // gWt0[ip*256+i] = W0[i][ip]
__device__ float    gWt1[256 * 256];
__device__ float    gWt2[256 * 128];         // gWt2[i*128+j] = W2[j][i]
__device__ unsigned gPartK[2][16][MERGEW];   // per-chunk top-100 keys
__device__ int      gPartI[2][16][MERGEW];   // local candidate ids
__device__ float    gPartV[2][16][MERGEW];   // candidate values

struct TK {                                   // select scratch (shared)
    unsigned hist[256];
    int      selI[KEEP];
    int      eq[256];
    int      cnt[4];                          // 0:G 1:E 2:byte 3:newr
};

__device__ __forceinline__ unsigned fkey(float f) {
    unsigned u = __float_as_uint(f);
    return (u & 0x80000000u) ? ~u : (u | 0x80000000u);
}
__device__ __forceinline__ float ikey(unsigned k) {
    return __uint_as_float((k & 0x80000000u) ? (k & 0x7FFFFFFFu) : ~k);
}
__device__ __forceinline__ float ftanh(float x) {
    float e = __expf(2.f * x);
    return 1.f - __fdividef(2.f, e + 1.f);
}

// ---- exact top-KEEP radix select; selI[] = selected indices sorted ascending ----
template <int NT>
__device__ void topk(const unsigned* keys, int n, TK* t, int tid) {
    unsigned prefix = 0u;
    int r = KEEP;
    const int lane = tid & 31;
    const int nIter = (n + NT - 1) / NT;
    #pragma unroll
    for (int shift = 24; shift >= 0; shift -= 8) {
        if (tid < 256) t->hist[tid] = 0u;
        __syncthreads();
        unsigned pm = (shift == 24) ? 0u : (0xFFFFFFFFu << (shift + 8));
        for (int it = 0; it < nIter; it++) {
            int idx = it * NT + tid;
            unsigned k = (idx < n) ? keys[idx] : 0u;
            bool act = (idx < n) && ((k & pm) == prefix);
            unsigned bin = (k >> shift) & 255u;
            unsigned am = __ballot_sync(FULL, act);
            if (act) {
                unsigned peers = __match_any_sync(am, bin);
                if (lane == __ffs(peers) - 1) atomicAdd(&t->hist[bin], __popc(peers));
            }
        }
        __syncthreads();
        if (tid < 32) {                      // warp-0: suffix scan + threshold find
            int base = lane * 8;
            unsigned s[8]; unsigned run = 0u;
            #pragma unroll
            for (int j = 7; j >= 0; j--) { run += t->hist[base + j]; s[j] = run; }
            unsigned tt = run;
            #pragma unroll
            for (int off = 1; off < 32; off <<= 1) {
                unsigned uu = __shfl_down_sync(FULL, tt, off);
                if (lane + off < 32) tt += uu;
            }
            unsigned above = tt - run;
            unsigned cum0 = s[0] + above;
            unsigned nxt7 = __shfl_down_sync(FULL, cum0, 1);
            if (lane == 31) nxt7 = 0u;
            #pragma unroll
            for (int j = 0; j < 8; j++) {
                unsigned cj = s[j] + above;
                unsigned nj = (j < 7) ? (s[j + 1] + above) : nxt7;
                if (cj >= (unsigned)r && nj < (unsigned)r) {
                    t->cnt[2] = base + j;
                    t->cnt[3] = r - (int)nj;
                }
            }
        }
        __syncthreads();
        prefix |= ((unsigned)t->cnt[2]) << shift;
        r = t->cnt[3];
    }
    unsigned T = prefix;
    if (tid == 0) { t->cnt[0] = 0; t->cnt[1] = 0; }
    __syncthreads();
    for (int idx = tid; idx < n; idx += NT) {
        unsigned k = keys[idx];
        if (k > T)       { int pp = atomicAdd(&t->cnt[0], 1); t->selI[pp] = idx; }
        else if (k == T) { int pp = atomicAdd(&t->cnt[1], 1); if (pp < 256) t->eq[pp] = idx; }
    }
    __syncthreads();
    if (tid == 0) {                          // ties: smallest indices win
        int G = t->cnt[0], E = KEEP - G;
        int ne = t->cnt[1] < 256 ? t->cnt[1] : 256;
        for (int e = 0; e < E; e++) {
            int bmin = 0x7FFFFFFF, bp = 0;
            for (int q = 0; q < ne; q++) if (t->eq[q] < bmin) { bmin = t->eq[q]; bp = q; }
            t->selI[G + e] = bmin; t->eq[bp] = 0x7FFFFFFF;
        }
    }
    __syncthreads();
    int myIdx = 0, rank = 0;                 // deterministic: sort by index asc
    if (tid < KEEP) {
        myIdx = t->selI[tid];
        for (int q = 0; q < KEEP; q++) rank += (t->selI[q] < myIdx) ? 1 : 0;
    }
    __syncthreads();
    if (tid < KEEP) t->selI[rank] = myIdx;
    __syncthreads();
}

// ========== k1: U precompute (blocks 0-95, no shuffles) + W transposes (96-135) ==========
__global__ void __launch_bounds__(256) kPrep(const float* __restrict__ W0,
                                             const float* __restrict__ W1,
                                             const float* __restrict__ W2,
                                             const float* __restrict__ s10,
                                             const float* __restrict__ s11,
                                             const float* __restrict__ s12) {
    __shared__ float tile[64][65];           // transpose tile / s1 row (aliased ok)
    const int tid = threadIdx.x, g = blockIdx.x;
    if (g < 96) {
        // one block per (layer l, hidden unit h): U[l][h][i] = sum_o s1[h,o] * W[o,i]
        int l = g >> 5, h = g & 31;
        const float* W  = (l == 0) ? W0 : (l == 1) ? W1 : W2;
        const float* s1 = (l == 0) ? s10 : (l == 1) ? s11 : s12;
        int fo = (l == 2) ? 128 : 256;
        float* srow = &tile[0][0];
        if (tid < fo) srow[tid] = s1[h * fo + tid];   // coalesced row load
        __syncthreads();
        float acc = 0.f;
        #pragma unroll 8
        for (int o = 0; o < fo; o++)
            acc = fmaf(srow[o], W[o * 256 + tid], acc);   // SMEM broadcast + coalesced LDG
        gU[l][h][tid] = acc;
    } else {
        const float* src; float* dst; int t, srcld, dstld;
        int gg = g - 96;
        if (gg < 16)      { src = W0; dst = gWt0; t = gg;      srcld = 256; dstld = 256; }
        else if (gg < 32) { src = W1; dst = gWt1; t = gg - 16; srcld = 256; dstld = 256; }
        else              { src = W2; dst = gWt2; t = gg - 32; srcld = 256; dstld = 128; }
        int ncol = srcld >> 6;
        int tr = t / ncol, tc = t % ncol;
        for (int idx = tid; idx < 4096; idx += 256) {
            int r = idx >> 6, c = idx & 63;
            tile[r][c] = src[(tr * 64 + r) * srcld + tc * 64 + c];
        }
        __syncthreads();
        for (int idx = tid; idx < 4096; idx += 256) {
            int r = idx >> 6, c = idx & 63;
            dst[(tc * 64 + r) * dstld + tr * 64 + c] = tile[c][r];
        }
    }
}

// ========== k2: redundant select0 + stage-1 chunk scoring + local top (288 blocks) ==========
__global__ void __launch_bounds__(256) kScoreA(const float* __restrict__ x,
                                               const float* __restrict__ b10,
                                               const float* __restrict__ w20,
                                               const float* __restrict__ bb20,
                                               const float* __restrict__ b11,
                                               const float* __restrict__ w21,
                                               const float* __restrict__ bb21) {
    __shared__ unsigned skeys[1536];
    __shared__ float    svals[1536];
    __shared__ TK tk;
    __shared__ int   ip[KEEP];
    __shared__ float cv[KEEP];
    __shared__ float b1c[32], w2c[32];
    const int g = blockIdx.x, tid = threadIdx.x;
    const int b = g & 15, chunk = g >> 4;
    const int kn = (chunk < 10) ? 6 : 5;
    const int k0 = (chunk < 10) ? chunk * 6 : 60 + (chunk - 10) * 5;
    float Ureg[32];

    // --- redundant select0 over 256 layer-0 candidates ---
    if (tid < 32) { b1c[tid] = b10[tid]; w2c[tid] = w20[tid]; }
    #pragma unroll
    for (int h = 0; h < 32; h++) Ureg[h] = gU[0][h][tid];
    __syncthreads();
    float c0v = x[b * 256 + tid];
    float acc0 = 0.f;
    #pragma unroll
    for (int h = 0; h < 32; h++) {
        float t = fmaf(c0v, Ureg[h], b1c[h]);
        acc0 = fmaf(w2c[h], fmaxf(t, 0.f), acc0);
    }
    skeys[tid] = fkey(acc0 + bb20[0]);
    __syncthreads();
    topk<256>(skeys, 256, &tk, tid);
    if (tid < KEEP) {
        int i0 = tk.selI[tid];
        ip[tid] = i0;
        cv[tid] = x[b * 256 + i0];
    }

    // --- stage-1 chunk scoring ---
    if (tid < 32) { b1c[tid] = b11[tid]; w2c[tid] = w21[tid]; }
    #pragma unroll
    for (int h = 0; h < 32; h++) Ureg[h] = gU[1][h][tid];
    __syncthreads();
    float b2 = bb21[0];
    for (int kk = 0; kk < kn; kk++) {
        int k = k0 + kk;
        float v = ftanh(gWt0[ip[k] * 256 + tid] * cv[k]);      // coalesced gather
        float a = 0.f;
        #pragma unroll
        for (int h = 0; h < 32; h++) {
            float t = fmaf(v, Ureg[h], b1c[h]);
            a = fmaf(w2c[h], fmaxf(t, 0.f), a);
        }
        skeys[kk * 256 + tid] = fkey(a + b2);
        svals[kk * 256 + tid] = v;
    }
    __syncthreads();
    topk<256>(skeys, kn * 256, &tk, tid);
    if (tid < KEEP) {
        int j = tk.selI[tid];
        int slot = chunk * KEEP + tid;
        gPartK[0][b][slot] = skeys[j];
        gPartI[0][b][slot] = k0 * 256 + j;
        gPartV[0][b][slot] = svals[j];
    }
}

// ========== k3: redundant merge + stage-2 chunk scoring + local top (288 blocks) ==========
__global__ void __launch_bounds__(256) kScoreB(const float* __restrict__ b12,
                                               const float* __restrict__ w22,
                                               const float* __restrict__ bb22) {
    __shared__ unsigned skeys[MERGEW];        // merge then reuse for scoring (1536)
    __shared__ float    svals[1536];
    __shared__ TK tk;
    __shared__ int   ip[KEEP];
    __shared__ float cv[KEEP];
    __shared__ float b1c[32], w2c[32];
    const int g = blockIdx.x, tid = threadIdx.x;
    const int b = g & 15, chunk = g >> 4;
    const int kn = (chunk < 10) ? 6 : 5;
    const int k0 = (chunk < 10) ? chunk * 6 : 60 + (chunk - 10) * 5;
    float Ureg[32];

    // --- redundant merge of stage-1 partials ---
    for (int idx = tid; idx < MERGEW; idx += 256) skeys[idx] = gPartK[0][b][idx];
    if (tid < 32) { b1c[tid] = b12[tid]; w2c[tid] = w22[tid]; }
    #pragma unroll
    for (int h = 0; h < 32; h++) Ureg[h] = gU[2][h][tid];
    __syncthreads();
    topk<256>(skeys, MERGEW, &tk, tid);
    if (tid < KEEP) {
        int j = tk.selI[tid];
        ip[tid] = gPartI[0][b][j] & 255;
        cv[tid] = gPartV[0][b][j];
    }
    __syncthreads();

    // --- stage-2 chunk scoring ---
    float b2 = bb22[0];
    for (int kk = 0; kk < kn; kk++) {
        int k = k0 + kk;
        float v = ftanh(gWt1[ip[k] * 256 + tid] * cv[k]);
        float a = 0.f;
        #pragma unroll
        for (int h = 0; h < 32; h++) {
            float t = fmaf(v, Ureg[h], b1c[h]);
            a = fmaf(w2c[h], fmaxf(t, 0.f), a);
        }
        skeys[kk * 256 + tid] = fkey(a + b2);
        svals[kk * 256 + tid] = v;
    }
    __syncthreads();
    topk<256>(skeys, kn * 256, &tk, tid);
    if (tid < KEEP) {
        int j = tk.selI[tid];
        int slot = chunk * KEEP + tid;
        gPartK[1][b][slot] = skeys[j];
        gPartI[1][b][slot] = k0 * 256 + j;
        gPartV[1][b][slot] = svals[j];
    }
}

// ========== k4: final merge + softmax + output (16 blocks, 512 thr) ==========
__global__ void __launch_bounds__(512) kFinal(float* __restrict__ out) {
    __shared__ unsigned skeys[MERGEW];
    __shared__ TK tk;
    __shared__ int   ipk[KEEP];
    __shared__ float wc[KEEP], selS[KEEP], red[4];
    const int b = blockIdx.x, tid = threadIdx.x;
    const int lane = tid & 31;
    for (int idx = tid; idx < MERGEW; idx += 512) skeys[idx] = gPartK[1][b][idx];
    __syncthreads();
    topk<512>(skeys, MERGEW, &tk, tid);
    if (tid < KEEP) {
        int j = tk.selI[tid];
        ipk[tid]  = gPartI[1][b][j] & 255;
        wc[tid]   = gPartV[1][b][j];             // value (no tanh after last layer)
        selS[tid] = ikey(skeys[j]);              // exact selection score
    }
    __syncthreads();
    float s = (tid < KEEP) ? selS[tid] : -INFINITY;
    if (tid < 128) {
        float m = s;
        #pragma unroll
        for (int o = 16; o; o >>= 1) m = fmaxf(m, __shfl_xor_sync(FULL, m, o));
        if (lane == 0) red[tid >> 5] = m;
    }
    __syncthreads();
    float mx = fmaxf(fmaxf(red[0], red[1]), fmaxf(red[2], red[3]));
    float e = (tid < KEEP) ? __expf(s - mx) : 0.f;
    __syncthreads();
    if (tid < 128) {
        float z = e;
        #pragma unroll
        for (int o = 16; o; o >>= 1) z += __shfl_xor_sync(FULL, z, o);
        if (lane == 0) red[tid >> 5] = z;
    }
    __syncthreads();
    float Z = red[0] + red[1] + red[2] + red[3];
    if (tid < KEEP) wc[tid] = wc[tid] * (e / Z);
    __syncthreads();
    if (tid < 128) {
        float acc = 0.f;
        #pragma unroll 4
        for (int q = 0; q < KEEP; q++)
            acc = fmaf(wc[q], gWt2[ipk[q] * 128 + tid], acc);   // coalesced
        out[b * 128 + tid] = acc;
    }
}

// ---------------------------------------------------------------------------------
extern "C" void kernel_launch(void* const* d_in, const int* in_sizes, int n_in,
                              void* d_out, int out_size) {
    const float *x, *W[3], *sw1[3], *sb1[3], *sw2[3], *sb2[3];
    x = (const float*)d_in[0];
    if (n_in >= 16 && in_sizes[2] == 65536) {
        for (int l = 0; l < 3; l++) W[l] = (const float*)d_in[1 + l];
        for (int l = 0; l < 3; l++) {
            int base = 4 + l * 4;
            sw1[l] = (const float*)d_in[base];     sb1[l] = (const float*)d_in[base + 1];
            sw2[l] = (const float*)d_in[base + 2]; sb2[l] = (const float*)d_in[base + 3];
        }
    } else {
        for (int l = 0; l < 3; l++) {
            int base = 1 + l * 5;
            W[l]   = (const float*)d_in[base];
            sw1[l] = (const float*)d_in[base + 1]; sb1[l] = (const float*)d_in[base + 2];
            sw2[l] = (const float*)d_in[base + 3]; sb2[l] = (const float*)d_in[base + 4];
        }
    }
    float* out = (float*)d_out;

    kPrep  <<<136, 256>>>(W[0], W[1], W[2], sw1[0], sw1[1], sw1[2]);
    kScoreA<<<288, 256>>>(x, sb1[0], sw2[0], sb2[0], sb1[1], sw2[1], sb2[1]);
    kScoreB<<<288, 256>>>(sb1[2], sw2[2], sb2[2]);
    kFinal <<<16, 512>>>(out);
}

// round 12
// speedup vs baseline: 1.3976x; 1.3976x over previous
#include <cuda_runtime.h>
#include <math.h>

#define KEEP 100
#define NCHUNK 9
#define MERGEW 900
#define FULL 0xFFFFFFFFu

// ---------------- device scratch (no allocations) ----------------
__device__ float    gU[3][32][256];          // U_l[h][i] = sum_o sw1[h,o]*W_l[o,i]
__device__ float    gWt0[256 * 256];         // gWt0[ip*256+i] = W0[i][ip]
__device__ float    gWt1[256 * 256];
__device__ float    gWt2[256 * 128];         // gWt2[i*128+j] = W2[j][i]
__device__ unsigned gPartK[2][16][MERGEW];   // per-chunk top-100 keys
__device__ int      gPartI[2][16][MERGEW];   // global candidate ids
__device__ float    gPartV[2][16][MERGEW];   // candidate values

struct TK {                                   // select scratch (shared)
    unsigned hist[256];
    int      selI[KEEP];
    int      eq[256];
    int      cnt[4];                          // 0:G 1:E 2:byte 3:newr
};

__device__ __forceinline__ unsigned fkey(float f) {
    unsigned u = __float_as_uint(f);
    return (u & 0x80000000u) ? ~u : (u | 0x80000000u);
}
__device__ __forceinline__ float ikey(unsigned k) {
    return __uint_as_float((k & 0x80000000u) ? (k & 0x7FFFFFFFu) : ~k);
}
__device__ __forceinline__ float ftanh(float x) {
    float e = __expf(2.f * x);
    return 1.f - __fdividef(2.f, e + 1.f);
}

// ---- exact top-KEEP radix select; selI[] = selected indices sorted ascending ----
template <int NT>
__device__ void topk(const unsigned* keys, int n, TK* t, int tid) {
    unsigned prefix = 0u;
    int r = KEEP;
    const int lane = tid & 31;
    const int nIter = (n + NT - 1) / NT;
    #pragma unroll
    for (int shift = 24; shift >= 0; shift -= 8) {
        if (tid < 256) t->hist[tid] = 0u;
        __syncthreads();
        unsigned pm = (shift == 24) ? 0u : (0xFFFFFFFFu << (shift + 8));
        for (int it = 0; it < nIter; it++) {
            int idx = it * NT + tid;
            unsigned k = (idx < n) ? keys[idx] : 0u;
            bool act = (idx < n) && ((k & pm) == prefix);
            unsigned bin = (k >> shift) & 255u;
            unsigned am = __ballot_sync(FULL, act);
            if (act) {
                unsigned peers = __match_any_sync(am, bin);
                if (lane == __ffs(peers) - 1) atomicAdd(&t->hist[bin], __popc(peers));
            }
        }
        __syncthreads();
        if (tid < 32) {                      // warp-0: suffix scan + threshold find
            int base = lane * 8;
            unsigned s[8]; unsigned run = 0u;
            #pragma unroll
            for (int j = 7; j >= 0; j--) { run += t->hist[base + j]; s[j] = run; }
            unsigned tt = run;
            #pragma unroll
            for (int off = 1; off < 32; off <<= 1) {
                unsigned uu = __shfl_down_sync(FULL, tt, off);
                if (lane + off < 32) tt += uu;
            }
            unsigned above = tt - run;
            unsigned cum0 = s[0] + above;
            unsigned nxt7 = __shfl_down_sync(FULL, cum0, 1);
            if (lane == 31) nxt7 = 0u;
            #pragma unroll
            for (int j = 0; j < 8; j++) {
                unsigned cj = s[j] + above;
                unsigned nj = (j < 7) ? (s[j + 1] + above) : nxt7;
                if (cj >= (unsigned)r && nj < (unsigned)r) {
                    t->cnt[2] = base + j;
                    t->cnt[3] = r - (int)nj;
                }
            }
        }
        __syncthreads();
        prefix |= ((unsigned)t->cnt[2]) << shift;
        r = t->cnt[3];
    }
    unsigned T = prefix;
    if (tid == 0) { t->cnt[0] = 0; t->cnt[1] = 0; }
    __syncthreads();
    for (int idx = tid; idx < n; idx += NT) {
        unsigned k = keys[idx];
        if (k > T)       { int pp = atomicAdd(&t->cnt[0], 1); t->selI[pp] = idx; }
        else if (k == T) { int pp = atomicAdd(&t->cnt[1], 1); if (pp < 256) t->eq[pp] = idx; }
    }
    __syncthreads();
    if (tid == 0) {                          // ties: smallest indices win
        int G = t->cnt[0], E = KEEP - G;
        int ne = t->cnt[1] < 256 ? t->cnt[1] : 256;
        for (int e = 0; e < E; e++) {
            int bmin = 0x7FFFFFFF, bp = 0;
            for (int q = 0; q < ne; q++) if (t->eq[q] < bmin) { bmin = t->eq[q]; bp = q; }
            t->selI[G + e] = bmin; t->eq[bp] = 0x7FFFFFFF;
        }
    }
    __syncthreads();
    int myIdx = 0, rank = 0;                 // deterministic: sort by index asc
    if (tid < KEEP) {
        myIdx = t->selI[tid];
        for (int q = 0; q < KEEP; q++) rank += (t->selI[q] < myIdx) ? 1 : 0;
    }
    __syncthreads();
    if (tid < KEEP) t->selI[rank] = myIdx;
    __syncthreads();
}

// ========== k1 (R8-exact): U precompute (blocks 0-23) + W transposes (24-63) ==========
__global__ void __launch_bounds__(256) kPrep(const float* __restrict__ W0,
                                             const float* __restrict__ W1,
                                             const float* __restrict__ W2,
                                             const float* __restrict__ s10,
                                             const float* __restrict__ s11,
                                             const float* __restrict__ s12) {
    __shared__ float tile[64][65];
    const int tid = threadIdx.x, g = blockIdx.x;
    const int lane = tid & 31;
    if (g < 24) {
        int l = g >> 3, ic = g & 7;
        int ii = ic * 32 + lane;
        const float* W  = (l == 0) ? W0 : (l == 1) ? W1 : W2;
        const float* s1 = (l == 0) ? s10 : (l == 1) ? s11 : s12;
        int fo = (l == 2) ? 128 : 256;
        for (int hh = 0; hh < 4; hh++) {
            int h = (tid >> 5) + hh * 8;
            float acc = 0.f;
            for (int oc = 0; oc < fo; oc += 32) {
                float sv = s1[h * fo + oc + lane];
                #pragma unroll
                for (int j = 0; j < 32; j++) {
                    float svj = __shfl_sync(FULL, sv, j);
                    acc = fmaf(svj, W[(oc + j) * 256 + ii], acc);
                }
            }
            gU[l][h][ii] = acc;
        }
    } else {
        const float* src; float* dst; int t, srcld, dstld;
        if (g < 40)      { src = W0; dst = gWt0; t = g - 24; srcld = 256; dstld = 256; }
        else if (g < 56) { src = W1; dst = gWt1; t = g - 40; srcld = 256; dstld = 256; }
        else             { src = W2; dst = gWt2; t = g - 56; srcld = 256; dstld = 128; }
        int ncol = srcld >> 6;
        int tr = t / ncol, tc = t % ncol;
        for (int idx = tid; idx < 4096; idx += 256) {
            int r = idx >> 6, c = idx & 63;
            tile[r][c] = src[(tr * 64 + r) * srcld + tc * 64 + c];
        }
        __syncthreads();
        for (int idx = tid; idx < 4096; idx += 256) {
            int r = idx >> 6, c = idx & 63;
            dst[(tc * 64 + r) * dstld + tr * 64 + c] = tile[c][r];
        }
    }
}

// ========== k2: redundant select0 + stage-1 chunk scoring + local top (144 blocks, 512 thr) ==========
__global__ void __launch_bounds__(512) kScoreA(const float* __restrict__ x,
                                               const float* __restrict__ b10,
                                               const float* __restrict__ w20,
                                               const float* __restrict__ bb20,
                                               const float* __restrict__ b11,
                                               const float* __restrict__ w21,
                                               const float* __restrict__ bb21) {
    __shared__ unsigned skeys[3072];
    __shared__ float    svals[3072];
    __shared__ TK tk;
    __shared__ int   ip[KEEP];
    __shared__ float cv[KEEP];
    __shared__ float b1c[32], w2c[32];
    const int g = blockIdx.x, tid = threadIdx.x;
    const int b = g & 15, chunk = g >> 4;            // chunk 0..8
    const int kn = (chunk == 0) ? 12 : 11;           // 12 + 8*11 = 100
    const int k0 = (chunk == 0) ? 0 : 12 + (chunk - 1) * 11;
    const int i = tid & 255, half = tid >> 8;
    float Ureg[32];

    // --- redundant select0 over 256 layer-0 candidates (half 0 computes) ---
    if (tid < 32) { b1c[tid] = b10[tid]; w2c[tid] = w20[tid]; }
    __syncthreads();
    if (tid < 256) {
        #pragma unroll
        for (int h = 0; h < 32; h++) Ureg[h] = gU[0][h][tid];
        float c0v = x[b * 256 + tid];
        float acc0 = 0.f;
        #pragma unroll
        for (int h = 0; h < 32; h++) {
            float t = fmaf(c0v, Ureg[h], b1c[h]);
            acc0 = fmaf(w2c[h], fmaxf(t, 0.f), acc0);
        }
        skeys[tid] = fkey(acc0 + bb20[0]);
    }
    __syncthreads();
    topk<512>(skeys, 256, &tk, tid);
    if (tid < KEEP) {
        int i0 = tk.selI[tid];
        ip[tid] = i0;
        cv[tid] = x[b * 256 + i0];
    }

    // --- stage-1 chunk scoring (both halves) ---
    if (tid < 32) { b1c[tid] = b11[tid]; w2c[tid] = w21[tid]; }
    #pragma unroll
    for (int h = 0; h < 32; h++) Ureg[h] = gU[1][h][i];
    __syncthreads();
    float b2 = bb21[0];
    for (int kk = half; kk < kn; kk += 2) {
        int k = k0 + kk;
        float v = ftanh(gWt0[ip[k] * 256 + i] * cv[k]);        // coalesced gather
        float a = 0.f;
        #pragma unroll
        for (int h = 0; h < 32; h++) {
            float t = fmaf(v, Ureg[h], b1c[h]);
            a = fmaf(w2c[h], fmaxf(t, 0.f), a);
        }
        skeys[kk * 256 + i] = fkey(a + b2);
        svals[kk * 256 + i] = v;
    }
    __syncthreads();
    topk<512>(skeys, kn * 256, &tk, tid);
    if (tid < KEEP) {
        int j = tk.selI[tid];
        int slot = chunk * KEEP + tid;
        gPartK[0][b][slot] = skeys[j];
        gPartI[0][b][slot] = k0 * 256 + j;
        gPartV[0][b][slot] = svals[j];
    }
}

// ========== k3: redundant merge + stage-2 chunk scoring + local top (144 blocks, 512 thr) ==========
__global__ void __launch_bounds__(512) kScoreB(const float* __restrict__ b12,
                                               const float* __restrict__ w22,
                                               const float* __restrict__ bb22) {
    __shared__ unsigned skeys[3072];          // merge (900) then scoring (3072)
    __shared__ float    svals[3072];
    __shared__ TK tk;
    __shared__ int   ip[KEEP];
    __shared__ float cv[KEEP];
    __shared__ float b1c[32], w2c[32];
    const int g = blockIdx.x, tid = threadIdx.x;
    const int b = g & 15, chunk = g >> 4;
    const int kn = (chunk == 0) ? 12 : 11;
    const int k0 = (chunk == 0) ? 0 : 12 + (chunk - 1) * 11;
    const int i = tid & 255, half = tid >> 8;
    float Ureg[32];

    // --- redundant merge of stage-1 partials (900) ---
    for (int idx = tid; idx < MERGEW; idx += 512) skeys[idx] = gPartK[0][b][idx];
    if (tid < 32) { b1c[tid] = b12[tid]; w2c[tid] = w22[tid]; }
    #pragma unroll
    for (int h = 0; h < 32; h++) Ureg[h] = gU[2][h][i];
    __syncthreads();
    topk<512>(skeys, MERGEW, &tk, tid);
    if (tid < KEEP) {
        int j = tk.selI[tid];
        ip[tid] = gPartI[0][b][j] & 255;
        cv[tid] = gPartV[0][b][j];
    }
    __syncthreads();

    // --- stage-2 chunk scoring ---
    float b2 = bb22[0];
    for (int kk = half; kk < kn; kk += 2) {
        int k = k0 + kk;
        float v = ftanh(gWt1[ip[k] * 256 + i] * cv[k]);
        float a = 0.f;
        #pragma unroll
        for (int h = 0; h < 32; h++) {
            float t = fmaf(v, Ureg[h], b1c[h]);
            a = fmaf(w2c[h], fmaxf(t, 0.f), a);
        }
        skeys[kk * 256 + i] = fkey(a + b2);
        svals[kk * 256 + i] = v;
    }
    __syncthreads();
    topk<512>(skeys, kn * 256, &tk, tid);
    if (tid < KEEP) {
        int j = tk.selI[tid];
        int slot = chunk * KEEP + tid;
        gPartK[1][b][slot] = skeys[j];
        gPartI[1][b][slot] = k0 * 256 + j;
        gPartV[1][b][slot] = svals[j];
    }
}

// ========== k4: final merge + softmax + output (16 blocks, 512 thr) ==========
__global__ void __launch_bounds__(512) kFinal(float* __restrict__ out) {
    __shared__ unsigned skeys[MERGEW];
    __shared__ TK tk;
    __shared__ int   ipk[KEEP];
    __shared__ float wc[KEEP], selS[KEEP], red[4];
    const int b = blockIdx.x, tid = threadIdx.x;
    const int lane = tid & 31;
    for (int idx = tid; idx < MERGEW; idx += 512) skeys[idx] = gPartK[1][b][idx];
    __syncthreads();
    topk<512>(skeys, MERGEW, &tk, tid);
    if (tid < KEEP) {
        int j = tk.selI[tid];
        ipk[tid]  = gPartI[1][b][j] & 255;
        wc[tid]   = gPartV[1][b][j];             // value (no tanh after last layer)
        selS[tid] = ikey(skeys[j]);              // exact selection score
    }
    __syncthreads();
    float s = (tid < KEEP) ? selS[tid] : -INFINITY;
    if (tid < 128) {
        float m = s;
        #pragma unroll
        for (int o = 16; o; o >>= 1) m = fmaxf(m, __shfl_xor_sync(FULL, m, o));
        if (lane == 0) red[tid >> 5] = m;
    }
    __syncthreads();
    float mx = fmaxf(fmaxf(red[0], red[1]), fmaxf(red[2], red[3]));
    float e = (tid < KEEP) ? __expf(s - mx) : 0.f;
    __syncthreads();
    if (tid < 128) {
        float z = e;
        #pragma unroll
        for (int o = 16; o; o >>= 1) z += __shfl_xor_sync(FULL, z, o);
        if (lane == 0) red[tid >> 5] = z;
    }
    __syncthreads();
    float Z = red[0] + red[1] + red[2] + red[3];
    if (tid < KEEP) wc[tid] = wc[tid] * (e / Z);
    __syncthreads();
    if (tid < 128) {
        float acc = 0.f;
        #pragma unroll 4
        for (int q = 0; q < KEEP; q++)
            acc = fmaf(wc[q], gWt2[ipk[q] * 128 + tid], acc);   // coalesced
        out[b * 128 + tid] = acc;
    }
}

// ---------------------------------------------------------------------------------
extern "C" void kernel_launch(void* const* d_in, const int* in_sizes, int n_in,
                              void* d_out, int out_size) {
    const float *x, *W[3], *sw1[3], *sb1[3], *sw2[3], *sb2[3];
    x = (const float*)d_in[0];
    if (n_in >= 16 && in_sizes[2] == 65536) {
        for (int l = 0; l < 3; l++) W[l] = (const float*)d_in[1 + l];
        for (int l = 0; l < 3; l++) {
            int base = 4 + l * 4;
            sw1[l] = (const float*)d_in[base];     sb1[l] = (const float*)d_in[base + 1];
            sw2[l] = (const float*)d_in[base + 2]; sb2[l] = (const float*)d_in[base + 3];
        }
    } else {
        for (int l = 0; l < 3; l++) {
            int base = 1 + l * 5;
            W[l]   = (const float*)d_in[base];
            sw1[l] = (const float*)d_in[base + 1]; sb1[l] = (const float*)d_in[base + 2];
            sw2[l] = (const float*)d_in[base + 3]; sb2[l] = (const float*)d_in[base + 4];
        }
    }
    float* out = (float*)d_out;

    kPrep  <<<64, 256>>>(W[0], W[1], W[2], sw1[0], sw1[1], sw1[2]);
    kScoreA<<<144, 512>>>(x, sb1[0], sw2[0], sb2[0], sb1[1], sw2[1], sb2[1]);
    kScoreB<<<144, 512>>>(sb1[2], sw2[2], sb2[2]);
    kFinal <<<16, 512>>>(out);
}

// round 13
// speedup vs baseline: 1.5057x; 1.0774x over previous
#include <cuda_runtime.h>
#include <math.h>

#define KEEP 100
#define NCHUNK 9
#define MERGEW 900
#define FULL 0xFFFFFFFFu

// ---------------- device scratch (no allocations) ----------------
__device__ float    gU[3][32][256];          // U_l[h][i] = sum_o sw1[h,o]*W_l[o,i]
__device__ float    gWt0[256 * 256];         // gWt0[ip*256+i] = W0[i][ip]
__device__ float    gWt1[256 * 256];
__device__ float    gWt2[256 * 128];         // gWt2[i*128+j] = W2[j][i]
__device__ unsigned gPartK[2][16][MERGEW];   // per-chunk top-100 keys
__device__ int      gPartI[2][16][MERGEW];   // global candidate ids
__device__ float    gPartV[2][16][MERGEW];   // candidate values

struct TK {                                   // select scratch (shared)
    unsigned hist[2][256];                    // double-buffered bins
    int      selI[KEEP];
    unsigned eq[256];                         // (lowbyte<<24) | (0xFFFFFF - idx)
    int      cnt[4];                          // 0:G 1:E 2:byte 3:newr
};

__device__ __forceinline__ unsigned fkey(float f) {
    unsigned u = __float_as_uint(f);
    return (u & 0x80000000u) ? ~u : (u | 0x80000000u);
}
__device__ __forceinline__ float ikey(unsigned k) {
    return __uint_as_float((k & 0x80000000u) ? (k & 0x7FFFFFFFu) : ~k);
}
__device__ __forceinline__ float ftanh(float x) {
    float e = __expf(2.f * x);
    return 1.f - __fdividef(2.f, e + 1.f);
}

// ---- exact top-KEEP select: 3 radix passes + byte-resolve in collect ----
// selI[] = selected indices sorted ascending. Order identical to full 4-pass
// radix: top-KEEP by key desc, ties broken by smallest index.
template <int NT>
__device__ void topk(const unsigned* keys, int n, TK* t, int tid) {
    unsigned prefix = 0u;                     // accumulates bits [31:8]
    int r = KEEP;
    const int lane = tid & 31;
    const int nIter = (n + NT - 1) / NT;
    if (tid < 256) { t->hist[0][tid] = 0u; t->hist[1][tid] = 0u; }
    __syncthreads();
    #pragma unroll
    for (int p = 0; p < 3; p++) {
        const int shift = 24 - 8 * p;
        unsigned* cur = t->hist[p & 1];
        unsigned pm = (p == 0) ? 0u : (0xFFFFFFFFu << (shift + 8));
        for (int it = 0; it < nIter; it++) {
            int idx = it * NT + tid;
            unsigned k = (idx < n) ? keys[idx] : 0u;
            bool act = (idx < n) && ((k & pm) == (prefix & pm));
            unsigned bin = (k >> shift) & 255u;
            unsigned am = __ballot_sync(FULL, act);
            if (act) {
                unsigned peers = __match_any_sync(am, bin);
                if (lane == __ffs(peers) - 1) atomicAdd(&cur[bin], __popc(peers));
            }
        }
        if (tid < 256) t->hist[(p + 1) & 1][tid] = 0u;   // clear next buffer now
        __syncthreads();
        if (tid < 32) {                      // warp-0: suffix scan + threshold find
            int base = lane * 8;
            unsigned s[8]; unsigned run = 0u;
            #pragma unroll
            for (int j = 7; j >= 0; j--) { run += cur[base + j]; s[j] = run; }
            unsigned tt = run;
            #pragma unroll
            for (int off = 1; off < 32; off <<= 1) {
                unsigned uu = __shfl_down_sync(FULL, tt, off);
                if (lane + off < 32) tt += uu;
            }
            unsigned above = tt - run;
            unsigned cum0 = s[0] + above;
            unsigned nxt7 = __shfl_down_sync(FULL, cum0, 1);
            if (lane == 31) nxt7 = 0u;
            #pragma unroll
            for (int j = 0; j < 8; j++) {
                unsigned cj = s[j] + above;
                unsigned nj = (j < 7) ? (s[j + 1] + above) : nxt7;
                if (cj >= (unsigned)r && nj < (unsigned)r) {
                    t->cnt[2] = base + j;
                    t->cnt[3] = r - (int)nj;
                }
            }
        }
        __syncthreads();
        prefix |= ((unsigned)t->cnt[2]) << shift;
        r = t->cnt[3];
    }
    // prefix holds the exact top-24 bits of the KEEP-th key; r = needed from that bin
    if (tid == 0) { t->cnt[0] = 0; t->cnt[1] = 0; }
    __syncthreads();
    for (int idx = tid; idx < n; idx += NT) {
        unsigned k = keys[idx];
        unsigned hi = k & 0xFFFFFF00u;
        if (hi > prefix)       { int pp = atomicAdd(&t->cnt[0], 1); t->selI[pp] = idx; }
        else if (hi == prefix) {
            int pp = atomicAdd(&t->cnt[1], 1);
            if (pp < 256) t->eq[pp] = ((k & 0xFFu) << 24) | (0xFFFFFFu - (unsigned)idx);
        }
    }
    __syncthreads();
    if (tid == 0) {                          // resolve last byte + index ties
        int G = t->cnt[0], E = KEEP - G;
        int ne = t->cnt[1] < 256 ? t->cnt[1] : 256;
        for (int e = 0; e < E; e++) {        // pick max (byte, then smallest idx)
            unsigned best = 0u; int bp = 0;
            for (int q = 0; q < ne; q++) if (t->eq[q] > best) { best = t->eq[q]; bp = q; }
            t->selI[G + e] = (int)(0xFFFFFFu - (best & 0xFFFFFFu));
            t->eq[bp] = 0u;
        }
    }
    __syncthreads();
    int myIdx = 0, rank = 0;                 // deterministic: sort by index asc
    if (tid < KEEP) {
        myIdx = t->selI[tid];
        for (int q = 0; q < KEEP; q++) rank += (t->selI[q] < myIdx) ? 1 : 0;
    }
    __syncthreads();
    if (tid < KEEP) t->selI[rank] = myIdx;
    __syncthreads();
}

// ========== k1 (R8-exact): U precompute (blocks 0-23) + W transposes (24-63) ==========
__global__ void __launch_bounds__(256) kPrep(const float* __restrict__ W0,
                                             const float* __restrict__ W1,
                                             const float* __restrict__ W2,
                                             const float* __restrict__ s10,
                                             const float* __restrict__ s11,
                                             const float* __restrict__ s12) {
    __shared__ float tile[64][65];
    const int tid = threadIdx.x, g = blockIdx.x;
    const int lane = tid & 31;
    if (g < 24) {
        int l = g >> 3, ic = g & 7;
        int ii = ic * 32 + lane;
        const float* W  = (l == 0) ? W0 : (l == 1) ? W1 : W2;
        const float* s1 = (l == 0) ? s10 : (l == 1) ? s11 : s12;
        int fo = (l == 2) ? 128 : 256;
        for (int hh = 0; hh < 4; hh++) {
            int h = (tid >> 5) + hh * 8;
            float acc = 0.f;
            for (int oc = 0; oc < fo; oc += 32) {
                float sv = s1[h * fo + oc + lane];
                #pragma unroll
                for (int j = 0; j < 32; j++) {
                    float svj = __shfl_sync(FULL, sv, j);
                    acc = fmaf(svj, W[(oc + j) * 256 + ii], acc);
                }
            }
            gU[l][h][ii] = acc;
        }
    } else {
        const float* src; float* dst; int t, srcld, dstld;
        if (g < 40)      { src = W0; dst = gWt0; t = g - 24; srcld = 256; dstld = 256; }
        else if (g < 56) { src = W1; dst = gWt1; t = g - 40; srcld = 256; dstld = 256; }
        else             { src = W2; dst = gWt2; t = g - 56; srcld = 256; dstld = 128; }
        int ncol = srcld >> 6;
        int tr = t / ncol, tc = t % ncol;
        for (int idx = tid; idx < 4096; idx += 256) {
            int r = idx >> 6, c = idx & 63;
            tile[r][c] = src[(tr * 64 + r) * srcld + tc * 64 + c];
        }
        __syncthreads();
        for (int idx = tid; idx < 4096; idx += 256) {
            int r = idx >> 6, c = idx & 63;
            dst[(tc * 64 + r) * dstld + tr * 64 + c] = tile[c][r];
        }
    }
}

// ========== k2: redundant select0 + stage-1 chunk scoring + local top (144 blocks, 512 thr) ==========
__global__ void __launch_bounds__(512) kScoreA(const float* __restrict__ x,
                                               const float* __restrict__ b10,
                                               const float* __restrict__ w20,
                                               const float* __restrict__ bb20,
                                               const float* __restrict__ b11,
                                               const float* __restrict__ w21,
                                               const float* __restrict__ bb21) {
    __shared__ unsigned skeys[3072];
    __shared__ float    svals[3072];
    __shared__ TK tk;
    __shared__ int   ip[KEEP];
    __shared__ float cv[KEEP];
    __shared__ float b1c[32], w2c[32];
    const int g = blockIdx.x, tid = threadIdx.x;
    const int b = g & 15, chunk = g >> 4;            // chunk 0..8
    const int kn = (chunk == 0) ? 12 : 11;           // 12 + 8*11 = 100
    const int k0 = (chunk == 0) ? 0 : 12 + (chunk - 1) * 11;
    const int i = tid & 255, half = tid >> 8;
    float Ureg[32];

    // --- redundant select0 over 256 layer-0 candidates ---
    if (tid < 32) { b1c[tid] = b10[tid]; w2c[tid] = w20[tid]; }
    __syncthreads();
    if (tid < 256) {
        #pragma unroll
        for (int h = 0; h < 32; h++) Ureg[h] = gU[0][h][tid];
        float c0v = x[b * 256 + tid];
        float acc0 = 0.f;
        #pragma unroll
        for (int h = 0; h < 32; h++) {
            float t = fmaf(c0v, Ureg[h], b1c[h]);
            acc0 = fmaf(w2c[h], fmaxf(t, 0.f), acc0);
        }
        skeys[tid] = fkey(acc0 + bb20[0]);
    }
    __syncthreads();
    topk<512>(skeys, 256, &tk, tid);
    if (tid < KEEP) {
        int i0 = tk.selI[tid];
        ip[tid] = i0;
        cv[tid] = x[b * 256 + i0];
    }

    // --- stage-1 chunk scoring (both halves) ---
    if (tid < 32) { b1c[tid] = b11[tid]; w2c[tid] = w21[tid]; }
    #pragma unroll
    for (int h = 0; h < 32; h++) Ureg[h] = gU[1][h][i];
    __syncthreads();
    float b2 = bb21[0];
    for (int kk = half; kk < kn; kk += 2) {
        int k = k0 + kk;
        float v = ftanh(gWt0[ip[k] * 256 + i] * cv[k]);        // coalesced gather
        float a = 0.f;
        #pragma unroll
        for (int h = 0; h < 32; h++) {
            float t = fmaf(v, Ureg[h], b1c[h]);
            a = fmaf(w2c[h], fmaxf(t, 0.f), a);
        }
        skeys[kk * 256 + i] = fkey(a + b2);
        svals[kk * 256 + i] = v;
    }
    __syncthreads();
    topk<512>(skeys, kn * 256, &tk, tid);
    if (tid < KEEP) {
        int j = tk.selI[tid];
        int slot = chunk * KEEP + tid;
        gPartK[0][b][slot] = skeys[j];
        gPartI[0][b][slot] = k0 * 256 + j;
        gPartV[0][b][slot] = svals[j];
    }
}

// ========== k3: redundant merge + stage-2 chunk scoring + local top (144 blocks, 512 thr) ==========
__global__ void __launch_bounds__(512) kScoreB(const float* __restrict__ b12,
                                               const float* __restrict__ w22,
                                               const float* __restrict__ bb22) {
    __shared__ unsigned skeys[3072];          // merge (900) then scoring (3072)
    __shared__ float    svals[3072];
    __shared__ TK tk;
    __shared__ int   ip[KEEP];
    __shared__ float cv[KEEP];
    __shared__ float b1c[32], w2c[32];
    const int g = blockIdx.x, tid = threadIdx.x;
    const int b = g & 15, chunk = g >> 4;
    const int kn = (chunk == 0) ? 12 : 11;
    const int k0 = (chunk == 0) ? 0 : 12 + (chunk - 1) * 11;
    const int i = tid & 255, half = tid >> 8;
    float Ureg[32];

    // --- redundant merge of stage-1 partials (900, vectorized load) ---
    {
        const uint4* src4 = (const uint4*)&gPartK[0][b][0];
        for (int idx = tid; idx < MERGEW / 4; idx += 512)
            ((uint4*)skeys)[idx] = src4[idx];
    }
    if (tid < 32) { b1c[tid] = b12[tid]; w2c[tid] = w22[tid]; }
    #pragma unroll
    for (int h = 0; h < 32; h++) Ureg[h] = gU[2][h][i];
    __syncthreads();
    topk<512>(skeys, MERGEW, &tk, tid);
    if (tid < KEEP) {
        int j = tk.selI[tid];
        ip[tid] = gPartI[0][b][j] & 255;
        cv[tid] = gPartV[0][b][j];
    }
    __syncthreads();

    // --- stage-2 chunk scoring ---
    float b2 = bb22[0];
    for (int kk = half; kk < kn; kk += 2) {
        int k = k0 + kk;
        float v = ftanh(gWt1[ip[k] * 256 + i] * cv[k]);
        float a = 0.f;
        #pragma unroll
        for (int h = 0; h < 32; h++) {
            float t = fmaf(v, Ureg[h], b1c[h]);
            a = fmaf(w2c[h], fmaxf(t, 0.f), a);
        }
        skeys[kk * 256 + i] = fkey(a + b2);
        svals[kk * 256 + i] = v;
    }
    __syncthreads();
    topk<512>(skeys, kn * 256, &tk, tid);
    if (tid < KEEP) {
        int j = tk.selI[tid];
        int slot = chunk * KEEP + tid;
        gPartK[1][b][slot] = skeys[j];
        gPartI[1][b][slot] = k0 * 256 + j;
        gPartV[1][b][slot] = svals[j];
    }
}

// ========== k4: final merge + softmax + output (16 blocks, 512 thr) ==========
__global__ void __launch_bounds__(512) kFinal(float* __restrict__ out) {
    __shared__ unsigned skeys[MERGEW];
    __shared__ TK tk;
    __shared__ int   ipk[KEEP];
    __shared__ float wc[KEEP], selS[KEEP], red[4];
    const int b = blockIdx.x, tid = threadIdx.x;
    const int lane = tid & 31;
    {
        const uint4* src4 = (const uint4*)&gPartK[1][b][0];
        for (int idx = tid; idx < MERGEW / 4; idx += 512)
            ((uint4*)skeys)[idx] = src4[idx];
    }
    __syncthreads();
    topk<512>(skeys, MERGEW, &tk, tid);
    if (tid < KEEP) {
        int j = tk.selI[tid];
        ipk[tid]  = gPartI[1][b][j] & 255;
        wc[tid]   = gPartV[1][b][j];             // value (no tanh after last layer)
        selS[tid] = ikey(skeys[j]);              // exact selection score
    }
    __syncthreads();
    float s = (tid < KEEP) ? selS[tid] : -INFINITY;
    if (tid < 128) {
        float m = s;
        #pragma unroll
        for (int o = 16; o; o >>= 1) m = fmaxf(m, __shfl_xor_sync(FULL, m, o));
        if (lane == 0) red[tid >> 5] = m;
    }
    __syncthreads();
    float mx = fmaxf(fmaxf(red[0], red[1]), fmaxf(red[2], red[3]));
    float e = (tid < KEEP) ? __expf(s - mx) : 0.f;
    __syncthreads();
    if (tid < 128) {
        float z = e;
        #pragma unroll
        for (int o = 16; o; o >>= 1) z += __shfl_xor_sync(FULL, z, o);
        if (lane == 0) red[tid >> 5] = z;
    }
    __syncthreads();
    float Z = red[0] + red[1] + red[2] + red[3];
    if (tid < KEEP) wc[tid] = wc[tid] * (e / Z);
    __syncthreads();
    if (tid < 128) {
        float acc = 0.f;
        #pragma unroll 4
        for (int q = 0; q < KEEP; q++)
            acc = fmaf(wc[q], gWt2[ipk[q] * 128 + tid], acc);   // coalesced
        out[b * 128 + tid] = acc;
    }
}

// ---------------------------------------------------------------------------------
extern "C" void kernel_launch(void* const* d_in, const int* in_sizes, int n_in,
                              void* d_out, int out_size) {
    const float *x, *W[3], *sw1[3], *sb1[3], *sw2[3], *sb2[3];
    x = (const float*)d_in[0];
    if (n_in >= 16 && in_sizes[2] == 65536) {
        for (int l = 0; l < 3; l++) W[l] = (const float*)d_in[1 + l];
        for (int l = 0; l < 3; l++) {
            int base = 4 + l * 4;
            sw1[l] = (const float*)d_in[base];     sb1[l] = (const float*)d_in[base + 1];
            sw2[l] = (const float*)d_in[base + 2]; sb2[l] = (const float*)d_in[base + 3];
        }
    } else {
        for (int l = 0; l < 3; l++) {
            int base = 1 + l * 5;
            W[l]   = (const float*)d_in[base];
            sw1[l] = (const float*)d_in[base + 1]; sb1[l] = (const float*)d_in[base + 2];
            sw2[l] = (const float*)d_in[base + 3]; sb2[l] = (const float*)d_in[base + 4];
        }
    }
    float* out = (float*)d_out;

    kPrep  <<<64, 256>>>(W[0], W[1], W[2], sw1[0], sw1[1], sw1[2]);
    kScoreA<<<144, 512>>>(x, sb1[0], sw2[0], sb2[0], sb1[1], sw2[1], sb2[1]);
    kScoreB<<<144, 512>>>(sb1[2], sw2[2], sb2[2]);
    kFinal <<<16, 512>>>(out);
}